// round 11
// baseline (speedup 1.0000x reference)
#include <cuda_runtime.h>
#include <math.h>

#define NC 10
#define NG 8
#define TPB 256
#define WARPS (TPB / 32)
#define QCAP 256           // ring capacity per warp (power of 2)
#define BPC 60             // blocks per class
#define GRID (NC * BPC)

// Scratch (__device__ globals; zero-init at load; finalize resets for replays)
__device__ float g_S[NC * NG];
__device__ float g_V[NC * NG];
__device__ float g_count[NC];
__device__ unsigned g_ticket;

// Per-row accumulate: S_i += a_i;  V_i += a_i * (R - log a_i), R = sum log a_j
#define ACC(AQ, BQ)                                                             \
    {                                                                           \
        float a[NG] = {(AQ).x, (AQ).y, (AQ).z, (AQ).w,                          \
                       (BQ).x, (BQ).y, (BQ).z, (BQ).w};                         \
        float la[NG]; float R = 0.0f;                                           \
        _Pragma("unroll")                                                       \
        for (int g = 0; g < NG; ++g) { la[g] = __logf(a[g]); R += la[g]; }      \
        _Pragma("unroll")                                                       \
        for (int g = 0; g < NG; ++g) {                                          \
            s[g] += a[g];                                                       \
            v[g] = fmaf(a[g], R - la[g], v[g]);                                 \
        }                                                                       \
    }

// ---------------------------------------------------------------------------
// Single fused kernel: warp-compacted class scan + DEEP-BATCHED gather +
// last-block finalize. Each block owns ONE class. Warps scan labels (int4,
// warp-uniform bounds), ballot-compact matched row indices into a shared ring,
// and drain in 128-row batches: each thread hoists 4 rows (8 independent
// LDG.128) before computing, exposing ~4x the memory-level parallelism of the
// one-row-per-thread drain.
__global__ __launch_bounds__(TPB, 4) void k_all(const float* __restrict__ act,
                                                const int* __restrict__ labels,
                                                int N, float* __restrict__ out) {
    const int c    = blockIdx.x / BPC;
    const int b    = blockIdx.x % BPC;
    const int w    = threadIdx.x >> 5;
    const int lane = threadIdx.x & 31;
    const int want = c + 1;
    const size_t clsBase = (size_t)c * (size_t)N;

    __shared__ int qbuf[WARPS][QCAP];
    __shared__ float sh[2 * NG + 1];
    __shared__ bool amLast;
    __shared__ float pc[NC];

    if (threadIdx.x < 2 * NG + 1) sh[threadIdx.x] = 0.0f;
    __syncthreads();

    float s[NG] = {0,0,0,0,0,0,0,0};
    float v[NG] = {0,0,0,0,0,0,0,0};

    unsigned head = 0, tail = 0;   // warp-uniform ring cursors

    const int nq = N >> 2;
    const int4* lab4 = (const int4*)labels;
    const int gw     = b * WARPS + w;
    const int stride = BPC * WARPS * 32;
    const unsigned ltmask = (1u << lane) - 1u;

    // 4-deep batch: 128 queued rows, 4 rows per thread, loads hoisted.
    #define BATCH128()                                                          \
        {                                                                       \
            __syncwarp();                                                       \
            int i0 = qbuf[w][(head + lane)      & (QCAP - 1)];                  \
            int i1 = qbuf[w][(head + lane + 32) & (QCAP - 1)];                  \
            int i2 = qbuf[w][(head + lane + 64) & (QCAP - 1)];                  \
            int i3 = qbuf[w][(head + lane + 96) & (QCAP - 1)];                  \
            head += 128;                                                        \
            const float4* p0 = (const float4*)(act + (clsBase + (size_t)i0) * NG); \
            const float4* p1 = (const float4*)(act + (clsBase + (size_t)i1) * NG); \
            const float4* p2 = (const float4*)(act + (clsBase + (size_t)i2) * NG); \
            const float4* p3 = (const float4*)(act + (clsBase + (size_t)i3) * NG); \
            float4 x0 = p0[0], y0 = p0[1];                                      \
            float4 x1 = p1[0], y1 = p1[1];                                      \
            float4 x2 = p2[0], y2 = p2[1];                                      \
            float4 x3 = p3[0], y3 = p3[1];                                      \
            ACC(x0, y0) ACC(x1, y1) ACC(x2, y2) ACC(x3, y3)                     \
        }

    #define BATCH32()                                                           \
        {                                                                       \
            __syncwarp();                                                       \
            int idx = qbuf[w][(head + lane) & (QCAP - 1)];                      \
            head += 32;                                                         \
            const float4* r = (const float4*)(act + (clsBase + (size_t)idx) * NG); \
            float4 aq = r[0], bq = r[1];                                        \
            ACC(aq, bq)                                                         \
        }

    #define SLOT(LV, OFF)                                                      \
        {                                                                       \
            unsigned m = __ballot_sync(0xFFFFFFFFu, (LV) == want);              \
            if ((LV) == want)                                                   \
                qbuf[w][(tail + __popc(m & ltmask)) & (QCAP - 1)] = n + (OFF);  \
            tail += __popc(m);                                                  \
        }

    // Warp-uniform outer loop: 'base' is identical across the warp.
    for (int base = gw * 32; base < nq; base += stride) {
        int q = base + lane;
        int4 lb;
        if (q < nq) lb = lab4[q];
        else        { lb.x = 0; lb.y = 0; lb.z = 0; lb.w = 0; }
        int n = q << 2;
        SLOT(lb.x, 0) SLOT(lb.y, 1) SLOT(lb.z, 2) SLOT(lb.w, 3)
        // max enqueued since last check: 128 -> worst case 255 in ring (<= QCAP)
        while (tail - head >= 128) BATCH128()
    }

    // Scalar tail of labels (N % 4): warp 0 of block 0 per class, uniform loop.
    if (b == 0 && w == 0) {
        int tstart = nq << 2;
        for (int nb = tstart; nb < N; nb += 32) {
            int n = nb + lane;
            int lv = (n < N) ? labels[n] : 0;
            unsigned m = __ballot_sync(0xFFFFFFFFu, lv == want);
            if (lv == want)
                qbuf[w][(tail + __popc(m & ltmask)) & (QCAP - 1)] = n;
            tail += __popc(m);
            while (tail - head >= 128) BATCH128()
        }
    }

    // Drain 32-row batches, then the final <32 with predication.
    while (tail - head >= 32) BATCH32()
    {
        unsigned rem = tail - head;
        __syncwarp();
        int idx = (lane < (int)rem) ? qbuf[w][(head + lane) & (QCAP - 1)] : 0;
        if (lane < (int)rem) {
            const float4* r = (const float4*)(act + (clsBase + (size_t)idx) * NG);
            float4 aq = r[0], bq = r[1];
            ACC(aq, bq)
        }
    }
    #undef SLOT
    #undef BATCH32
    #undef BATCH128

    float cnt = (float)tail;   // warp-uniform: rows this warp enqueued

    // warp tree-reduce 16 values (all lanes alive here)
    #pragma unroll
    for (int o = 16; o > 0; o >>= 1) {
        #pragma unroll
        for (int g = 0; g < NG; ++g) {
            s[g] += __shfl_down_sync(0xFFFFFFFFu, s[g], o);
            v[g] += __shfl_down_sync(0xFFFFFFFFu, v[g], o);
        }
    }

    if (lane == 0) {
        #pragma unroll
        for (int g = 0; g < NG; ++g) {
            atomicAdd(&sh[g], s[g]);
            atomicAdd(&sh[NG + g], v[g]);
        }
        atomicAdd(&sh[2 * NG], cnt);
    }
    __syncthreads();
    if (threadIdx.x < NG) {
        atomicAdd(&g_S[c * NG + threadIdx.x], sh[threadIdx.x]);
        atomicAdd(&g_V[c * NG + threadIdx.x], sh[NG + threadIdx.x]);
    }
    if (threadIdx.x == 2 * NG) atomicAdd(&g_count[c], sh[2 * NG]);

    // ---- last-block finalize ----
    __threadfence();
    if (threadIdx.x == 0)
        amLast = (atomicAdd(&g_ticket, 1u) == (unsigned)(GRID - 1));
    __syncthreads();
    if (!amLast) return;

    int t = threadIdx.x;
    if (t < NC) pc[t] = 0.0f;
    __syncthreads();
    if (t < NC * NG) {
        float S = __ldcg(&g_S[t]);
        float V = __ldcg(&g_V[t]);
        float term = V / S - (float)(NG - 1) * logf(S);
        atomicAdd(&pc[t / NG], term);
    }
    __syncthreads();
    if (t == 0) {
        float num = 0.0f, vcnt = 0.0f;
        #pragma unroll
        for (int cc = 0; cc < NC; ++cc) {
            float cn = __ldcg(&g_count[cc]);
            if (cn >= 2.0f) { num += pc[cc]; vcnt += 1.0f; }
        }
        out[0] = num / (vcnt * (float)(NG * (NG - 1)));
        g_ticket = 0;                               // reset for next replay
    }
    __syncthreads();
    if (t < NC * NG) { g_S[t] = 0.0f; g_V[t] = 0.0f; }
    if (t < NC) g_count[t] = 0.0f;
}

// ---------------------------------------------------------------------------
extern "C" void kernel_launch(void* const* d_in, const int* in_sizes, int n_in,
                              void* d_out, int out_size) {
    const float* act  = (const float*)d_in[0];   // [C, N, G] float32
    const int* labels = (const int*)d_in[1];     // [N] int32
    const int N = in_sizes[1];

    k_all<<<GRID, TPB>>>(act, labels, N, (float*)d_out);
}